// round 1
// baseline (speedup 1.0000x reference)
#include <cuda_runtime.h>
#include <math.h>

// Problem constants
#define B_ 4
#define S_ 2048
#define D_ 1024
#define H_ 16
#define DK_ 64
#define M_ (B_ * S_)            // 8192 rows in the projection GEMMs

// Scratch (device globals; no allocation allowed)
__device__ float g_Q[B_ * H_ * S_ * DK_];   // head-split (b,h,s,d)
__device__ float g_K[B_ * H_ * S_ * DK_];
__device__ float g_V[B_ * H_ * S_ * DK_];
__device__ float g_ctx[B_ * S_ * D_];       // (b,s,h*64+d)

// ---------------------------------------------------------------------------
// SGEMM: C[M,N] = A[M,K] @ W[K,N] + bias, M=8192, N=K=1024, fp32.
// 128x128 block tile, 256 threads, 8x8 microtile, k-step 16.
// mode 0/1/2: write head-split into g_Q/g_K/g_V.  mode 3: A := g_ctx, write
// plain row-major into Cout (the harness output).
// ---------------------------------------------------------------------------
__global__ void __launch_bounds__(256) sgemm_kernel(
    const float* __restrict__ A, const float* __restrict__ W,
    const float* __restrict__ bias, float* __restrict__ Cout, int mode)
{
    __shared__ float As[128 * 16];   // [m][kk] row-major, 16-float rows
    __shared__ float Bs[16 * 128];   // [kk][n]

    const float* __restrict__ Ap = (mode == 3) ? g_ctx : A;

    const int tid = threadIdx.x;
    const int tx = tid & 15;         // n-direction (8 cols each)
    const int ty = tid >> 4;         // m-direction (8 rows each)
    const int bm = blockIdx.y * 128;
    const int bn = blockIdx.x * 128;

    float acc[8][8];
#pragma unroll
    for (int i = 0; i < 8; i++)
#pragma unroll
        for (int j = 0; j < 8; j++) acc[i][j] = 0.0f;

    for (int k0 = 0; k0 < 1024; k0 += 16) {
        // Load A tile (128x16) and W tile (16x128), 512 float4 each.
#pragma unroll
        for (int it = 0; it < 2; it++) {
            int idx = tid + it * 256;                 // float4 index 0..511
            int arow = idx >> 2, ac4 = idx & 3;       // A: 4 float4 per row
            float4 av = *(const float4*)(Ap + (size_t)(bm + arow) * 1024 + k0 + ac4 * 4);
            ((float4*)As)[arow * 4 + ac4] = av;
            int brow = idx >> 5, bc4 = idx & 31;      // W: 32 float4 per row
            float4 bv = *(const float4*)(W + (size_t)(k0 + brow) * 1024 + bn + bc4 * 4);
            ((float4*)Bs)[brow * 32 + bc4] = bv;
        }
        __syncthreads();

#pragma unroll
        for (int kk = 0; kk < 16; kk++) {
            float a[8];
#pragma unroll
            for (int i = 0; i < 8; i++) a[i] = As[(ty * 8 + i) * 16 + kk];
            float4 b0 = ((const float4*)Bs)[kk * 32 + tx * 2];
            float4 b1 = ((const float4*)Bs)[kk * 32 + tx * 2 + 1];
            float bb[8] = {b0.x, b0.y, b0.z, b0.w, b1.x, b1.y, b1.z, b1.w};
#pragma unroll
            for (int i = 0; i < 8; i++)
#pragma unroll
                for (int j = 0; j < 8; j++) acc[i][j] = fmaf(a[i], bb[j], acc[i][j]);
        }
        __syncthreads();
    }

    const int n0 = bn + tx * 8;
    if (mode == 3) {
        float bia[8];
#pragma unroll
        for (int j = 0; j < 8; j++) bia[j] = bias[n0 + j];
#pragma unroll
        for (int i = 0; i < 8; i++) {
            int m = bm + ty * 8 + i;
            float* crow = Cout + (size_t)m * 1024 + n0;
            float4 o0, o1;
            o0.x = acc[i][0] + bia[0]; o0.y = acc[i][1] + bia[1];
            o0.z = acc[i][2] + bia[2]; o0.w = acc[i][3] + bia[3];
            o1.x = acc[i][4] + bia[4]; o1.y = acc[i][5] + bia[5];
            o1.z = acc[i][6] + bia[6]; o1.w = acc[i][7] + bia[7];
            ((float4*)crow)[0] = o0;
            ((float4*)crow)[1] = o1;
        }
    } else {
        float* __restrict__ dstp = (mode == 0) ? g_Q : (mode == 1) ? g_K : g_V;
        // tx*8 never crosses a 64-col head boundary (8 | 64)
        const int h = n0 >> 6;
        const int d = n0 & 63;
#pragma unroll
        for (int i = 0; i < 8; i++) {
            int m = bm + ty * 8 + i;
            int b = m >> 11;            // m / 2048
            int s = m & 2047;
            float* drow = dstp + ((size_t)(b * H_ + h) * S_ + s) * DK_ + d;
#pragma unroll
            for (int j = 0; j < 8; j++) drow[j] = acc[i][j] + bias[n0 + j];
        }
    }
}

// ---------------------------------------------------------------------------
// Flash attention, fp32. One thread = one query row (DK=64 in registers).
// Block = 128 queries of one (b,h). K/V tiles (64x64) staged in smem;
// all threads read the same K/V element -> pure LDS broadcast.
// mask (B,1,1,S) masks keys; uniform per-key branch (no divergence).
// ---------------------------------------------------------------------------
__global__ void __launch_bounds__(128) attn_kernel(const int* __restrict__ mask)
{
    __shared__ float4 Ks[64][16];
    __shared__ float4 Vs[64][16];
    __shared__ int ms[64];

    const int tid = threadIdx.x;
    const int qt = blockIdx.x & 15;         // 16 q-tiles of 128
    const int bh = blockIdx.x >> 4;         // 0..63
    const int b = bh >> 4;                  // bh / H
    const int h = bh & 15;

    const float4* qrow = (const float4*)(g_Q + ((size_t)bh * S_ + qt * 128 + tid) * DK_);
    float4 q[16];
#pragma unroll
    for (int i = 0; i < 16; i++) q[i] = qrow[i];

    float4 acc[16];
#pragma unroll
    for (int i = 0; i < 16; i++) acc[i] = make_float4(0.f, 0.f, 0.f, 0.f);
    float mmax = -INFINITY;
    float l = 0.0f;
    const float scale = 0.125f;             // 1/sqrt(64)

    for (int kt = 0; kt < S_ / 64; kt++) {
        __syncthreads();
        const float4* Ksrc = (const float4*)(g_K + ((size_t)bh * S_ + kt * 64) * DK_);
        const float4* Vsrc = (const float4*)(g_V + ((size_t)bh * S_ + kt * 64) * DK_);
#pragma unroll
        for (int i = 0; i < 8; i++) {
            int idx = tid + i * 128;        // 1024 float4 per tile
            ((float4*)Ks)[idx] = Ksrc[idx];
            ((float4*)Vs)[idx] = Vsrc[idx];
        }
        if (tid < 64) ms[tid] = mask[b * S_ + kt * 64 + tid];
        __syncthreads();

        for (int k = 0; k < 64; k++) {
            if (!ms[k]) continue;           // uniform across block
            float4 s4 = make_float4(0.f, 0.f, 0.f, 0.f);
#pragma unroll
            for (int dd = 0; dd < 16; dd++) {
                float4 kv = Ks[k][dd];
                s4.x = fmaf(q[dd].x, kv.x, s4.x);
                s4.y = fmaf(q[dd].y, kv.y, s4.y);
                s4.z = fmaf(q[dd].z, kv.z, s4.z);
                s4.w = fmaf(q[dd].w, kv.w, s4.w);
            }
            float s = (s4.x + s4.y + s4.z + s4.w) * scale;
            if (s > mmax) {                 // rare (~log S per thread)
                float al = __expf(mmax - s);
                mmax = s;
                l *= al;
#pragma unroll
                for (int dd = 0; dd < 16; dd++) {
                    acc[dd].x *= al; acc[dd].y *= al;
                    acc[dd].z *= al; acc[dd].w *= al;
                }
            }
            float p = __expf(s - mmax);
            l += p;
#pragma unroll
            for (int dd = 0; dd < 16; dd++) {
                float4 vv = Vs[k][dd];
                acc[dd].x = fmaf(p, vv.x, acc[dd].x);
                acc[dd].y = fmaf(p, vv.y, acc[dd].y);
                acc[dd].z = fmaf(p, vv.z, acc[dd].z);
                acc[dd].w = fmaf(p, vv.w, acc[dd].w);
            }
        }
    }

    float inv = 1.0f / l;
    float4* dst = (float4*)(g_ctx + (size_t)(b * S_ + qt * 128 + tid) * D_ + h * DK_);
#pragma unroll
    for (int dd = 0; dd < 16; dd++) {
        float4 o = acc[dd];
        o.x *= inv; o.y *= inv; o.z *= inv; o.w *= inv;
        dst[dd] = o;
    }
}

// ---------------------------------------------------------------------------
// Launch: q,k,v,mask,Wq,bq,Wk,bk,Wv,bv,Wo,bo  (metadata order)
// ---------------------------------------------------------------------------
extern "C" void kernel_launch(void* const* d_in, const int* in_sizes, int n_in,
                              void* d_out, int out_size)
{
    const float* q    = (const float*)d_in[0];
    const float* k    = (const float*)d_in[1];
    const float* v    = (const float*)d_in[2];
    const int*   mask = (const int*)  d_in[3];
    const float* Wq   = (const float*)d_in[4];
    const float* bq   = (const float*)d_in[5];
    const float* Wk   = (const float*)d_in[6];
    const float* bk   = (const float*)d_in[7];
    const float* Wv   = (const float*)d_in[8];
    const float* bv   = (const float*)d_in[9];
    const float* Wo   = (const float*)d_in[10];
    const float* bo   = (const float*)d_in[11];
    float* out = (float*)d_out;

    dim3 ggrid(1024 / 128, M_ / 128);   // (8, 64)
    sgemm_kernel<<<ggrid, 256>>>(q, Wq, bq, nullptr, 0);
    sgemm_kernel<<<ggrid, 256>>>(k, Wk, bk, nullptr, 1);
    sgemm_kernel<<<ggrid, 256>>>(v, Wv, bv, nullptr, 2);
    attn_kernel<<<B_ * H_ * (S_ / 128), 128>>>(mask);
    sgemm_kernel<<<ggrid, 256>>>(nullptr, Wo, bo, out, 3);
}

// round 4
// speedup vs baseline: 2.9103x; 2.9103x over previous
#include <cuda_runtime.h>
#include <cstdint>
#include <math.h>

// Problem constants
#define B_ 4
#define S_ 2048
#define D_ 1024
#define H_ 16
#define DK_ 64
#define M_ (B_ * S_)

// Scratch (device globals; no allocation allowed)
__device__ float g_Q[B_ * H_ * S_ * DK_];   // head-split (b,h,s,d)
__device__ float g_K[B_ * H_ * S_ * DK_];
__device__ float g_V[B_ * H_ * S_ * DK_];
__device__ float g_ctx[B_ * S_ * D_];       // (b,s,h*64+d)

// ---------------------------------------------------------------------------
// tf32 helpers
// ---------------------------------------------------------------------------
__device__ __forceinline__ uint32_t f2tf(float x) {
    uint32_t u;
    asm("cvt.rna.tf32.f32 %0, %1;" : "=r"(u) : "f"(x));
    return u;
}

#define MMA_TF32(d, a, b)                                                     \
    asm volatile(                                                             \
        "mma.sync.aligned.m16n8k8.row.col.f32.tf32.tf32.f32 "                 \
        "{%0,%1,%2,%3}, {%4,%5,%6,%7}, {%8,%9}, {%0,%1,%2,%3};"               \
        : "+f"((d)[0]), "+f"((d)[1]), "+f"((d)[2]), "+f"((d)[3])              \
        : "r"((a)[0]), "r"((a)[1]), "r"((a)[2]), "r"((a)[3]),                 \
          "r"((b)[0]), "r"((b)[1]))

// ---------------------------------------------------------------------------
// tf32 GEMM: C[M,N] = A[M,1024] @ W[1024,N] + bias.  M=8192, N=1024.
// Block 128x128, 8 warps (warp tile 64x32), k-step 16, double-buffered smem.
// mode 0/1/2: head-split write to g_Q/g_K/g_V.  mode 3: A := g_ctx -> Cout.
// ---------------------------------------------------------------------------
#define SA_STRIDE 20     // 16 cols + pad: conflict-free a-frag loads
#define SB_STRIDE 136    // 128 cols + pad: conflict-free b-frag loads

__global__ void __launch_bounds__(256) gemm_tf32(
    const float* __restrict__ A, const float* __restrict__ W,
    const float* __restrict__ bias, float* __restrict__ Cout, int mode)
{
    __shared__ uint32_t sA[2][128 * SA_STRIDE];
    __shared__ uint32_t sB[2][16 * SB_STRIDE];

    const float* __restrict__ Ap = (mode == 3) ? g_ctx : A;

    const int tid  = threadIdx.x;
    const int lane = tid & 31, w = tid >> 5;
    const int g = lane >> 2, t = lane & 3;
    const int wm = (w >> 2) * 64;    // warp grid 2(m) x 4(n)
    const int wn = (w & 3) * 32;
    const int bm = blockIdx.y * 128, bn = blockIdx.x * 128;

    // staging indices: 512 float4 per tile, 2 per thread for A and for B
    const int mA0 = tid >> 2,        cA = tid & 3;   // A: 4 float4 per row
    const int mA1 = (tid + 256) >> 2;
    const int kB0 = tid >> 5,        nB = tid & 31;  // B: 32 float4 per row
    const int kB1 = (tid + 256) >> 5;

    float4 ra0, ra1, rb0, rb1;

    auto ldg = [&](int k0) {
        ra0 = *(const float4*)(Ap + (size_t)(bm + mA0) * 1024 + k0 + cA * 4);
        ra1 = *(const float4*)(Ap + (size_t)(bm + mA1) * 1024 + k0 + cA * 4);
        rb0 = *(const float4*)(W + (size_t)(k0 + kB0) * 1024 + bn + nB * 4);
        rb1 = *(const float4*)(W + (size_t)(k0 + kB1) * 1024 + bn + nB * 4);
    };
    auto sts = [&](int buf) {
        uint32_t* p;
        p = sA[buf] + mA0 * SA_STRIDE + cA * 4;
        p[0] = f2tf(ra0.x); p[1] = f2tf(ra0.y); p[2] = f2tf(ra0.z); p[3] = f2tf(ra0.w);
        p = sA[buf] + mA1 * SA_STRIDE + cA * 4;
        p[0] = f2tf(ra1.x); p[1] = f2tf(ra1.y); p[2] = f2tf(ra1.z); p[3] = f2tf(ra1.w);
        p = sB[buf] + kB0 * SB_STRIDE + nB * 4;
        p[0] = f2tf(rb0.x); p[1] = f2tf(rb0.y); p[2] = f2tf(rb0.z); p[3] = f2tf(rb0.w);
        p = sB[buf] + kB1 * SB_STRIDE + nB * 4;
        p[0] = f2tf(rb1.x); p[1] = f2tf(rb1.y); p[2] = f2tf(rb1.z); p[3] = f2tf(rb1.w);
    };

    float acc[4][4][4];
#pragma unroll
    for (int i = 0; i < 4; i++)
#pragma unroll
        for (int j = 0; j < 4; j++)
#pragma unroll
            for (int r = 0; r < 4; r++) acc[i][j][r] = 0.0f;

    ldg(0);
    sts(0);
    __syncthreads();

    for (int it = 0; it < 64; it++) {
        const int buf = it & 1;
        if (it < 63) ldg((it + 1) * 16);

        const uint32_t* pA = sA[buf];
        const uint32_t* pB = sB[buf];
#pragma unroll
        for (int hh = 0; hh < 2; hh++) {
            uint32_t af[4][4], bf[4][2];
#pragma unroll
            for (int mt = 0; mt < 4; mt++) {
                const uint32_t* q = pA + (wm + mt * 16 + g) * SA_STRIDE + 8 * hh + t;
                af[mt][0] = q[0];
                af[mt][1] = q[8 * SA_STRIDE];
                af[mt][2] = q[4];
                af[mt][3] = q[8 * SA_STRIDE + 4];
            }
#pragma unroll
            for (int nt = 0; nt < 4; nt++) {
                const int c0 = wn + nt * 8 + g;
                bf[nt][0] = pB[(8 * hh + t) * SB_STRIDE + c0];
                bf[nt][1] = pB[(8 * hh + t + 4) * SB_STRIDE + c0];
            }
#pragma unroll
            for (int mt = 0; mt < 4; mt++)
#pragma unroll
                for (int nt = 0; nt < 4; nt++)
                    MMA_TF32(acc[mt][nt], af[mt], bf[nt]);
        }

        if (it < 63) sts(buf ^ 1);
        __syncthreads();
    }

    // Epilogue
#pragma unroll
    for (int mt = 0; mt < 4; mt++) {
#pragma unroll
        for (int nt = 0; nt < 4; nt++) {
            const int r = bm + wm + mt * 16 + g;
            const int c = bn + wn + nt * 8 + 2 * t;
            const float b0 = bias[c], b1 = bias[c + 1];
            float2 v0, v1;
            v0.x = acc[mt][nt][0] + b0; v0.y = acc[mt][nt][1] + b1;
            v1.x = acc[mt][nt][2] + b0; v1.y = acc[mt][nt][3] + b1;
            if (mode == 3) {
                *(float2*)(Cout + (size_t)r * 1024 + c) = v0;
                *(float2*)(Cout + (size_t)(r + 8) * 1024 + c) = v1;
            } else {
                float* dst = (mode == 0) ? g_Q : (mode == 1) ? g_K : g_V;
                const int hh = c >> 6, d = c & 63;
                const int bb = r >> 11, s = r & 2047;
                *(float2*)(dst + ((size_t)(bb * 16 + hh) * 2048 + s) * 64 + d) = v0;
                *(float2*)(dst + ((size_t)(bb * 16 + hh) * 2048 + s + 8) * 64 + d) = v1;
            }
        }
    }
}

// ---------------------------------------------------------------------------
// Flash attention with tf32 mma. Block = 128 queries of one (b,h), 8 warps,
// warp = 16 query rows. Key tiles of 32. S = Q K^T via mma; online softmax on
// C-fragments; P -> smem (layout convert) -> P V via mma.
// ---------------------------------------------------------------------------
#define KV_STRIDE 72     // 64 cols + pad: conflict-free for both S and PV frags
#define P_STRIDE 36

__global__ void __launch_bounds__(256) attn_tf32(const int* __restrict__ mask)
{
    __shared__ uint32_t Ks[32 * KV_STRIDE];
    __shared__ uint32_t Vs[32 * KV_STRIDE];
    __shared__ uint32_t Ps[8][16 * P_STRIDE];
    __shared__ float fms[32];

    const int tid  = threadIdx.x;
    const int lane = tid & 31, w = tid >> 5;
    const int g = lane >> 2, t = lane & 3;
    const int qt = blockIdx.x & 15;
    const int bh = blockIdx.x >> 4;
    const int b  = bh >> 4, h = bh & 15;
    const int q0 = qt * 128 + w * 16;   // this warp's first query row (within b,h)

    // Q fragments, prescaled by 1/sqrt(64)
    uint32_t qf[8][4];
    {
        const float* Qp = g_Q + ((size_t)bh * 2048 + q0) * 64;
#pragma unroll
        for (int kk = 0; kk < 8; kk++) {
            qf[kk][0] = f2tf(0.125f * Qp[(size_t)g * 64 + 8 * kk + t]);
            qf[kk][1] = f2tf(0.125f * Qp[(size_t)(g + 8) * 64 + 8 * kk + t]);
            qf[kk][2] = f2tf(0.125f * Qp[(size_t)g * 64 + 8 * kk + t + 4]);
            qf[kk][3] = f2tf(0.125f * Qp[(size_t)(g + 8) * 64 + 8 * kk + t + 4]);
        }
    }

    float of[8][4];
#pragma unroll
    for (int i = 0; i < 8; i++)
#pragma unroll
        for (int r = 0; r < 4; r++) of[i][r] = 0.0f;
    float m0 = -1e30f, m1 = -1e30f, l0 = 0.0f, l1 = 0.0f;

    // staging indices: K/V tile = 32x64 fp32 = 512 float4; 2 per thread each
    const int r0 = tid >> 4, c4 = tid & 15;
    const int r1 = 16 + r0;

    for (int kt = 0; kt < 64; kt++) {
        __syncthreads();
        {
            const float4* Kg = (const float4*)(g_K + ((size_t)bh * 2048 + kt * 32) * 64);
            const float4* Vg = (const float4*)(g_V + ((size_t)bh * 2048 + kt * 32) * 64);
            float4 kv0 = Kg[r0 * 16 + c4], kv1 = Kg[r1 * 16 + c4];
            float4 vv0 = Vg[r0 * 16 + c4], vv1 = Vg[r1 * 16 + c4];
            uint32_t* p;
            p = Ks + r0 * KV_STRIDE + c4 * 4;
            p[0] = f2tf(kv0.x); p[1] = f2tf(kv0.y); p[2] = f2tf(kv0.z); p[3] = f2tf(kv0.w);
            p = Ks + r1 * KV_STRIDE + c4 * 4;
            p[0] = f2tf(kv1.x); p[1] = f2tf(kv1.y); p[2] = f2tf(kv1.z); p[3] = f2tf(kv1.w);
            p = Vs + r0 * KV_STRIDE + c4 * 4;
            p[0] = f2tf(vv0.x); p[1] = f2tf(vv0.y); p[2] = f2tf(vv0.z); p[3] = f2tf(vv0.w);
            p = Vs + r1 * KV_STRIDE + c4 * 4;
            p[0] = f2tf(vv1.x); p[1] = f2tf(vv1.y); p[2] = f2tf(vv1.z); p[3] = f2tf(vv1.w);
            if (tid < 32) fms[tid] = (float)mask[b * 2048 + kt * 32 + tid];
        }
        __syncthreads();

        // S = Q K^T  (16 q-rows x 32 keys per warp)
        float sf[4][4];
#pragma unroll
        for (int nt = 0; nt < 4; nt++)
#pragma unroll
            for (int r = 0; r < 4; r++) sf[nt][r] = 0.0f;
#pragma unroll
        for (int kk = 0; kk < 8; kk++) {
#pragma unroll
            for (int nt = 0; nt < 4; nt++) {
                uint32_t bf[2];
                bf[0] = Ks[(nt * 8 + g) * KV_STRIDE + 8 * kk + t];
                bf[1] = Ks[(nt * 8 + g) * KV_STRIDE + 8 * kk + t + 4];
                MMA_TF32(sf[nt], qf[kk], bf);
            }
        }

        // mask + row max (rows g and g+8; cols nt*8 + 2t, +1)
        float tmax0 = -1e30f, tmax1 = -1e30f;
#pragma unroll
        for (int nt = 0; nt < 4; nt++) {
            const int c = nt * 8 + 2 * t;
            const float mk0 = fms[c], mk1 = fms[c + 1];
            sf[nt][0] = (mk0 != 0.0f) ? sf[nt][0] : -1e30f;
            sf[nt][1] = (mk1 != 0.0f) ? sf[nt][1] : -1e30f;
            sf[nt][2] = (mk0 != 0.0f) ? sf[nt][2] : -1e30f;
            sf[nt][3] = (mk1 != 0.0f) ? sf[nt][3] : -1e30f;
            tmax0 = fmaxf(tmax0, fmaxf(sf[nt][0], sf[nt][1]));
            tmax1 = fmaxf(tmax1, fmaxf(sf[nt][2], sf[nt][3]));
        }
        tmax0 = fmaxf(tmax0, __shfl_xor_sync(0xffffffffu, tmax0, 1));
        tmax0 = fmaxf(tmax0, __shfl_xor_sync(0xffffffffu, tmax0, 2));
        tmax1 = fmaxf(tmax1, __shfl_xor_sync(0xffffffffu, tmax1, 1));
        tmax1 = fmaxf(tmax1, __shfl_xor_sync(0xffffffffu, tmax1, 2));

        const float nm0 = fmaxf(m0, tmax0), nm1 = fmaxf(m1, tmax1);
        const float al0 = __expf(m0 - nm0), al1 = __expf(m1 - nm1);
        m0 = nm0; m1 = nm1;

        uint32_t* Pw = Ps[w];
        float ps0 = 0.0f, ps1 = 0.0f;
#pragma unroll
        for (int nt = 0; nt < 4; nt++) {
            const int c = nt * 8 + 2 * t;
            const float p0 = __expf(sf[nt][0] - nm0);
            const float p1 = __expf(sf[nt][1] - nm0);
            const float p2 = __expf(sf[nt][2] - nm1);
            const float p3 = __expf(sf[nt][3] - nm1);
            ps0 += p0 + p1;
            ps1 += p2 + p3;
            Pw[g * P_STRIDE + c]           = f2tf(p0);
            Pw[g * P_STRIDE + c + 1]       = f2tf(p1);
            Pw[(g + 8) * P_STRIDE + c]     = f2tf(p2);
            Pw[(g + 8) * P_STRIDE + c + 1] = f2tf(p3);
        }
        ps0 += __shfl_xor_sync(0xffffffffu, ps0, 1);
        ps0 += __shfl_xor_sync(0xffffffffu, ps0, 2);
        ps1 += __shfl_xor_sync(0xffffffffu, ps1, 1);
        ps1 += __shfl_xor_sync(0xffffffffu, ps1, 2);
        l0 = l0 * al0 + ps0;
        l1 = l1 * al1 + ps1;
#pragma unroll
        for (int nt = 0; nt < 8; nt++) {
            of[nt][0] *= al0; of[nt][1] *= al0;
            of[nt][2] *= al1; of[nt][3] *= al1;
        }
        __syncwarp();   // P writes visible across the warp before frag loads

        // O += P V
#pragma unroll
        for (int kk = 0; kk < 4; kk++) {
            uint32_t pf[4];
            pf[0] = Pw[g * P_STRIDE + 8 * kk + t];
            pf[1] = Pw[(g + 8) * P_STRIDE + 8 * kk + t];
            pf[2] = Pw[g * P_STRIDE + 8 * kk + t + 4];
            pf[3] = Pw[(g + 8) * P_STRIDE + 8 * kk + t + 4];
#pragma unroll
            for (int nt = 0; nt < 8; nt++) {
                uint32_t bf[2];
                bf[0] = Vs[(8 * kk + t) * KV_STRIDE + nt * 8 + g];
                bf[1] = Vs[(8 * kk + t + 4) * KV_STRIDE + nt * 8 + g];
                MMA_TF32(of[nt], pf, bf);
            }
        }
        __syncwarp();   // P reads done before next iteration's writes
    }

    // Epilogue: normalize and write head-merged context
    const float inv0 = 1.0f / l0, inv1 = 1.0f / l1;
    const int s0 = qt * 128 + w * 16 + g;
    float* dst = g_ctx + ((size_t)b * 2048 + s0) * 1024 + h * 64;
#pragma unroll
    for (int nt = 0; nt < 8; nt++) {
        const int c = nt * 8 + 2 * t;
        float2 o0, o1;
        o0.x = of[nt][0] * inv0; o0.y = of[nt][1] * inv0;
        o1.x = of[nt][2] * inv1; o1.y = of[nt][3] * inv1;
        *(float2*)(dst + c) = o0;
        *(float2*)(dst + (size_t)8 * 1024 + c) = o1;
    }
}

// ---------------------------------------------------------------------------
// Launch: q,k,v,mask,Wq,bq,Wk,bk,Wv,bv,Wo,bo
// ---------------------------------------------------------------------------
extern "C" void kernel_launch(void* const* d_in, const int* in_sizes, int n_in,
                              void* d_out, int out_size)
{
    const float* q    = (const float*)d_in[0];
    const float* k    = (const float*)d_in[1];
    const float* v    = (const float*)d_in[2];
    const int*   mask = (const int*)  d_in[3];
    const float* Wq   = (const float*)d_in[4];
    const float* bq   = (const float*)d_in[5];
    const float* Wk   = (const float*)d_in[6];
    const float* bk   = (const float*)d_in[7];
    const float* Wv   = (const float*)d_in[8];
    const float* bv   = (const float*)d_in[9];
    const float* Wo   = (const float*)d_in[10];
    const float* bo   = (const float*)d_in[11];
    float* out = (float*)d_out;

    dim3 ggrid(1024 / 128, M_ / 128);   // (8, 64)
    gemm_tf32<<<ggrid, 256>>>(q, Wq, bq, nullptr, 0);
    gemm_tf32<<<ggrid, 256>>>(k, Wk, bk, nullptr, 1);
    gemm_tf32<<<ggrid, 256>>>(v, Wv, bv, nullptr, 2);
    attn_tf32<<<B_ * H_ * (S_ / 128), 256>>>(mask);
    gemm_tf32<<<ggrid, 256>>>(nullptr, Wo, bo, out, 3);
}

// round 5
// speedup vs baseline: 3.1636x; 1.0870x over previous
#include <cuda_runtime.h>
#include <cstdint>
#include <math.h>

// Problem constants
#define B_ 4
#define S_ 2048
#define D_ 1024
#define H_ 16
#define DK_ 64
#define M_ (B_ * S_)

// Scratch (device globals; no allocation allowed)
__device__ float g_Q[B_ * H_ * S_ * DK_];   // head-split (b,h,s,d)
__device__ float g_K[B_ * H_ * S_ * DK_];
__device__ float g_V[B_ * H_ * S_ * DK_];
__device__ float g_ctx[B_ * S_ * D_];       // (b,s,h*64+d)

// ---------------------------------------------------------------------------
// tf32 helpers
// ---------------------------------------------------------------------------
__device__ __forceinline__ uint32_t f2tf(float x) {
    uint32_t u;
    asm("cvt.rna.tf32.f32 %0, %1;" : "=r"(u) : "f"(x));
    return u;
}

#define MMA_TF32(d, a, b)                                                     \
    asm volatile(                                                             \
        "mma.sync.aligned.m16n8k8.row.col.f32.tf32.tf32.f32 "                 \
        "{%0,%1,%2,%3}, {%4,%5,%6,%7}, {%8,%9}, {%0,%1,%2,%3};"               \
        : "+f"((d)[0]), "+f"((d)[1]), "+f"((d)[2]), "+f"((d)[3])              \
        : "r"((a)[0]), "r"((a)[1]), "r"((a)[2]), "r"((a)[3]),                 \
          "r"((b)[0]), "r"((b)[1]))

// ---------------------------------------------------------------------------
// tf32 GEMM: C[M,N] = A[M,1024] @ W[1024,N] + bias.  M=8192, N=1024.
// Block 128x128, 8 warps (warp tile 64x32), k-step 16, double-buffered smem.
// mode 0/1/2: head-split write to g_Q/g_K/g_V.  mode 3: A := g_ctx -> Cout.
// (unchanged from the passing Round-4 kernel)
// ---------------------------------------------------------------------------
#define SA_STRIDE 20     // 16 cols + pad: conflict-free a-frag loads
#define SB_STRIDE 136    // 128 cols + pad: conflict-free b-frag loads

__global__ void __launch_bounds__(256) gemm_tf32(
    const float* __restrict__ A, const float* __restrict__ W,
    const float* __restrict__ bias, float* __restrict__ Cout, int mode)
{
    __shared__ uint32_t sA[2][128 * SA_STRIDE];
    __shared__ uint32_t sB[2][16 * SB_STRIDE];

    const float* __restrict__ Ap = (mode == 3) ? g_ctx : A;

    const int tid  = threadIdx.x;
    const int lane = tid & 31, w = tid >> 5;
    const int g = lane >> 2, t = lane & 3;
    const int wm = (w >> 2) * 64;    // warp grid 2(m) x 4(n)
    const int wn = (w & 3) * 32;
    const int bm = blockIdx.y * 128, bn = blockIdx.x * 128;

    // staging indices: 512 float4 per tile, 2 per thread for A and for B
    const int mA0 = tid >> 2,        cA = tid & 3;   // A: 4 float4 per row
    const int mA1 = (tid + 256) >> 2;
    const int kB0 = tid >> 5,        nB = tid & 31;  // B: 32 float4 per row
    const int kB1 = (tid + 256) >> 5;

    float4 ra0, ra1, rb0, rb1;

    auto ldg = [&](int k0) {
        ra0 = *(const float4*)(Ap + (size_t)(bm + mA0) * 1024 + k0 + cA * 4);
        ra1 = *(const float4*)(Ap + (size_t)(bm + mA1) * 1024 + k0 + cA * 4);
        rb0 = *(const float4*)(W + (size_t)(k0 + kB0) * 1024 + bn + nB * 4);
        rb1 = *(const float4*)(W + (size_t)(k0 + kB1) * 1024 + bn + nB * 4);
    };
    auto sts = [&](int buf) {
        uint32_t* p;
        p = sA[buf] + mA0 * SA_STRIDE + cA * 4;
        p[0] = f2tf(ra0.x); p[1] = f2tf(ra0.y); p[2] = f2tf(ra0.z); p[3] = f2tf(ra0.w);
        p = sA[buf] + mA1 * SA_STRIDE + cA * 4;
        p[0] = f2tf(ra1.x); p[1] = f2tf(ra1.y); p[2] = f2tf(ra1.z); p[3] = f2tf(ra1.w);
        p = sB[buf] + kB0 * SB_STRIDE + nB * 4;
        p[0] = f2tf(rb0.x); p[1] = f2tf(rb0.y); p[2] = f2tf(rb0.z); p[3] = f2tf(rb0.w);
        p = sB[buf] + kB1 * SB_STRIDE + nB * 4;
        p[0] = f2tf(rb1.x); p[1] = f2tf(rb1.y); p[2] = f2tf(rb1.z); p[3] = f2tf(rb1.w);
    };

    float acc[4][4][4];
#pragma unroll
    for (int i = 0; i < 4; i++)
#pragma unroll
        for (int j = 0; j < 4; j++)
#pragma unroll
            for (int r = 0; r < 4; r++) acc[i][j][r] = 0.0f;

    ldg(0);
    sts(0);
    __syncthreads();

    for (int it = 0; it < 64; it++) {
        const int buf = it & 1;
        if (it < 63) ldg((it + 1) * 16);

        const uint32_t* pA = sA[buf];
        const uint32_t* pB = sB[buf];
#pragma unroll
        for (int hh = 0; hh < 2; hh++) {
            uint32_t af[4][4], bf[4][2];
#pragma unroll
            for (int mt = 0; mt < 4; mt++) {
                const uint32_t* q = pA + (wm + mt * 16 + g) * SA_STRIDE + 8 * hh + t;
                af[mt][0] = q[0];
                af[mt][1] = q[8 * SA_STRIDE];
                af[mt][2] = q[4];
                af[mt][3] = q[8 * SA_STRIDE + 4];
            }
#pragma unroll
            for (int nt = 0; nt < 4; nt++) {
                const int c0 = wn + nt * 8 + g;
                bf[nt][0] = pB[(8 * hh + t) * SB_STRIDE + c0];
                bf[nt][1] = pB[(8 * hh + t + 4) * SB_STRIDE + c0];
            }
#pragma unroll
            for (int mt = 0; mt < 4; mt++)
#pragma unroll
                for (int nt = 0; nt < 4; nt++)
                    MMA_TF32(acc[mt][nt], af[mt], bf[nt]);
        }

        if (it < 63) sts(buf ^ 1);
        __syncthreads();
    }

    // Epilogue
#pragma unroll
    for (int mt = 0; mt < 4; mt++) {
#pragma unroll
        for (int nt = 0; nt < 4; nt++) {
            const int r = bm + wm + mt * 16 + g;
            const int c = bn + wn + nt * 8 + 2 * t;
            const float b0 = bias[c], b1 = bias[c + 1];
            float2 v0, v1;
            v0.x = acc[mt][nt][0] + b0; v0.y = acc[mt][nt][1] + b1;
            v1.x = acc[mt][nt][2] + b0; v1.y = acc[mt][nt][3] + b1;
            if (mode == 3) {
                *(float2*)(Cout + (size_t)r * 1024 + c) = v0;
                *(float2*)(Cout + (size_t)(r + 8) * 1024 + c) = v1;
            } else {
                float* dst = (mode == 0) ? g_Q : (mode == 1) ? g_K : g_V;
                const int hh = c >> 6, d = c & 63;
                const int bb = r >> 11, s = r & 2047;
                *(float2*)(dst + ((size_t)(bb * 16 + hh) * 2048 + s) * 64 + d) = v0;
                *(float2*)(dst + ((size_t)(bb * 16 + hh) * 2048 + s + 8) * 64 + d) = v1;
            }
        }
    }
}

// ---------------------------------------------------------------------------
// Flash attention with tf32 mma — mt=2 version.
// Block = 128 threads (4 warps); each warp owns 32 query rows (two m16 A-frag
// sets). K/V B-fragments are loaded ONCE per (kk,nt) and reused by both
// 16-row sets -> halves LDS per MMA vs the 16-row/warp version.
// Key tiles of 32. Math per q-row is bit-identical to the passing kernel.
// ---------------------------------------------------------------------------
#define KV_STRIDE 72     // 64 cols + pad: conflict-free frag loads
#define P_STRIDE 36

__global__ void __launch_bounds__(128, 2) attn_tf32(const int* __restrict__ mask)
{
    __shared__ uint32_t Ks[32 * KV_STRIDE];
    __shared__ uint32_t Vs[32 * KV_STRIDE];
    __shared__ uint32_t Ps[4][32 * P_STRIDE];
    __shared__ float fms[32];

    const int tid  = threadIdx.x;
    const int lane = tid & 31, w = tid >> 5;      // 4 warps
    const int g = lane >> 2, t = lane & 3;
    const int qt = blockIdx.x & 15;
    const int bh = blockIdx.x >> 4;
    const int b  = bh >> 4, h = bh & 15;
    const int q0 = qt * 128 + w * 32;             // warp's first query row

    // Q fragments for both 16-row sets, prescaled by 1/sqrt(64)
    uint32_t qf[2][8][4];
    {
        const float* Qp = g_Q + ((size_t)bh * 2048 + q0) * 64;
#pragma unroll
        for (int s = 0; s < 2; s++)
#pragma unroll
            for (int kk = 0; kk < 8; kk++) {
                qf[s][kk][0] = f2tf(0.125f * Qp[(size_t)(16 * s + g) * 64 + 8 * kk + t]);
                qf[s][kk][1] = f2tf(0.125f * Qp[(size_t)(16 * s + g + 8) * 64 + 8 * kk + t]);
                qf[s][kk][2] = f2tf(0.125f * Qp[(size_t)(16 * s + g) * 64 + 8 * kk + t + 4]);
                qf[s][kk][3] = f2tf(0.125f * Qp[(size_t)(16 * s + g + 8) * 64 + 8 * kk + t + 4]);
            }
    }

    float of[2][8][4];
#pragma unroll
    for (int s = 0; s < 2; s++)
#pragma unroll
        for (int i = 0; i < 8; i++)
#pragma unroll
            for (int r = 0; r < 4; r++) of[s][i][r] = 0.0f;
    float mr[2][2] = {{-1e30f, -1e30f}, {-1e30f, -1e30f}};
    float lr[2][2] = {{0.0f, 0.0f}, {0.0f, 0.0f}};

    for (int kt = 0; kt < 64; kt++) {
        __syncthreads();
        // Stage K/V tile (32 keys x 64 d = 512 float4; 4 per thread each)
        {
            const float4* Kg = (const float4*)(g_K + ((size_t)bh * 2048 + kt * 32) * 64);
            const float4* Vg = (const float4*)(g_V + ((size_t)bh * 2048 + kt * 32) * 64);
#pragma unroll
            for (int i = 0; i < 4; i++) {
                const int idx = tid + i * 128;     // 0..511
                const int row = idx >> 4, cc = idx & 15;
                float4 kv = Kg[idx];
                float4 vv = Vg[idx];
                uint32_t* p = Ks + row * KV_STRIDE + cc * 4;
                p[0] = f2tf(kv.x); p[1] = f2tf(kv.y); p[2] = f2tf(kv.z); p[3] = f2tf(kv.w);
                p = Vs + row * KV_STRIDE + cc * 4;
                p[0] = f2tf(vv.x); p[1] = f2tf(vv.y); p[2] = f2tf(vv.z); p[3] = f2tf(vv.w);
            }
            if (tid < 32) fms[tid] = (float)mask[b * 2048 + kt * 32 + tid];
        }
        __syncthreads();

        // S = Q K^T  (32 q-rows x 32 keys per warp; K-frags shared across s)
        float sf[2][4][4];
#pragma unroll
        for (int s = 0; s < 2; s++)
#pragma unroll
            for (int nt = 0; nt < 4; nt++)
#pragma unroll
                for (int r = 0; r < 4; r++) sf[s][nt][r] = 0.0f;
#pragma unroll
        for (int kk = 0; kk < 8; kk++) {
#pragma unroll
            for (int nt = 0; nt < 4; nt++) {
                uint32_t bf[2];
                bf[0] = Ks[(nt * 8 + g) * KV_STRIDE + 8 * kk + t];
                bf[1] = Ks[(nt * 8 + g) * KV_STRIDE + 8 * kk + t + 4];
                MMA_TF32(sf[0][nt], qf[0][kk], bf);
                MMA_TF32(sf[1][nt], qf[1][kk], bf);
            }
        }

        // Online softmax per 16-row set (rows g / g+8 within each set)
        uint32_t* Pw = Ps[w];
#pragma unroll
        for (int s = 0; s < 2; s++) {
            float tmax0 = -1e30f, tmax1 = -1e30f;
#pragma unroll
            for (int nt = 0; nt < 4; nt++) {
                const int c = nt * 8 + 2 * t;
                const float mk0 = fms[c], mk1 = fms[c + 1];
                sf[s][nt][0] = (mk0 != 0.0f) ? sf[s][nt][0] : -1e30f;
                sf[s][nt][1] = (mk1 != 0.0f) ? sf[s][nt][1] : -1e30f;
                sf[s][nt][2] = (mk0 != 0.0f) ? sf[s][nt][2] : -1e30f;
                sf[s][nt][3] = (mk1 != 0.0f) ? sf[s][nt][3] : -1e30f;
                tmax0 = fmaxf(tmax0, fmaxf(sf[s][nt][0], sf[s][nt][1]));
                tmax1 = fmaxf(tmax1, fmaxf(sf[s][nt][2], sf[s][nt][3]));
            }
            tmax0 = fmaxf(tmax0, __shfl_xor_sync(0xffffffffu, tmax0, 1));
            tmax0 = fmaxf(tmax0, __shfl_xor_sync(0xffffffffu, tmax0, 2));
            tmax1 = fmaxf(tmax1, __shfl_xor_sync(0xffffffffu, tmax1, 1));
            tmax1 = fmaxf(tmax1, __shfl_xor_sync(0xffffffffu, tmax1, 2));

            const float nm0 = fmaxf(mr[s][0], tmax0), nm1 = fmaxf(mr[s][1], tmax1);
            const float al0 = __expf(mr[s][0] - nm0), al1 = __expf(mr[s][1] - nm1);
            mr[s][0] = nm0; mr[s][1] = nm1;

            float ps0 = 0.0f, ps1 = 0.0f;
#pragma unroll
            for (int nt = 0; nt < 4; nt++) {
                const int c = nt * 8 + 2 * t;
                const float p0 = __expf(sf[s][nt][0] - nm0);
                const float p1 = __expf(sf[s][nt][1] - nm0);
                const float p2 = __expf(sf[s][nt][2] - nm1);
                const float p3 = __expf(sf[s][nt][3] - nm1);
                ps0 += p0 + p1;
                ps1 += p2 + p3;
                // paired stores (adjacent cols, 8B-aligned)
                *(uint2*)(Pw + (16 * s + g) * P_STRIDE + c)     = make_uint2(f2tf(p0), f2tf(p1));
                *(uint2*)(Pw + (16 * s + g + 8) * P_STRIDE + c) = make_uint2(f2tf(p2), f2tf(p3));
            }
            ps0 += __shfl_xor_sync(0xffffffffu, ps0, 1);
            ps0 += __shfl_xor_sync(0xffffffffu, ps0, 2);
            ps1 += __shfl_xor_sync(0xffffffffu, ps1, 1);
            ps1 += __shfl_xor_sync(0xffffffffu, ps1, 2);
            lr[s][0] = lr[s][0] * al0 + ps0;
            lr[s][1] = lr[s][1] * al1 + ps1;
#pragma unroll
            for (int nt = 0; nt < 8; nt++) {
                of[s][nt][0] *= al0; of[s][nt][1] *= al0;
                of[s][nt][2] *= al1; of[s][nt][3] *= al1;
            }
        }
        __syncwarp();   // P writes visible across the warp before frag loads

        // O += P V   (V-frags shared across s)
#pragma unroll
        for (int kk = 0; kk < 4; kk++) {
            uint32_t pf0[4], pf1[4];
            pf0[0] = Pw[g * P_STRIDE + 8 * kk + t];
            pf0[1] = Pw[(g + 8) * P_STRIDE + 8 * kk + t];
            pf0[2] = Pw[g * P_STRIDE + 8 * kk + t + 4];
            pf0[3] = Pw[(g + 8) * P_STRIDE + 8 * kk + t + 4];
            pf1[0] = Pw[(16 + g) * P_STRIDE + 8 * kk + t];
            pf1[1] = Pw[(16 + g + 8) * P_STRIDE + 8 * kk + t];
            pf1[2] = Pw[(16 + g) * P_STRIDE + 8 * kk + t + 4];
            pf1[3] = Pw[(16 + g + 8) * P_STRIDE + 8 * kk + t + 4];
#pragma unroll
            for (int nt = 0; nt < 8; nt++) {
                uint32_t bf[2];
                bf[0] = Vs[(8 * kk + t) * KV_STRIDE + nt * 8 + g];
                bf[1] = Vs[(8 * kk + t + 4) * KV_STRIDE + nt * 8 + g];
                MMA_TF32(of[0][nt], pf0, bf);
                MMA_TF32(of[1][nt], pf1, bf);
            }
        }
        // next tile's P writes are after two __syncthreads -> no extra sync needed
    }

    // Epilogue: normalize and write head-merged context
#pragma unroll
    for (int s = 0; s < 2; s++) {
        const float inv0 = 1.0f / lr[s][0], inv1 = 1.0f / lr[s][1];
        const int row = qt * 128 + w * 32 + 16 * s + g;
        float* dst = g_ctx + ((size_t)b * 2048 + row) * 1024 + h * 64;
#pragma unroll
        for (int nt = 0; nt < 8; nt++) {
            const int c = nt * 8 + 2 * t;
            float2 o0, o1;
            o0.x = of[s][nt][0] * inv0; o0.y = of[s][nt][1] * inv0;
            o1.x = of[s][nt][2] * inv1; o1.y = of[s][nt][3] * inv1;
            *(float2*)(dst + c) = o0;
            *(float2*)(dst + (size_t)8 * 1024 + c) = o1;
        }
    }
}

// ---------------------------------------------------------------------------
// Launch: q,k,v,mask,Wq,bq,Wk,bk,Wv,bv,Wo,bo
// ---------------------------------------------------------------------------
extern "C" void kernel_launch(void* const* d_in, const int* in_sizes, int n_in,
                              void* d_out, int out_size)
{
    const float* q    = (const float*)d_in[0];
    const float* k    = (const float*)d_in[1];
    const float* v    = (const float*)d_in[2];
    const int*   mask = (const int*)  d_in[3];
    const float* Wq   = (const float*)d_in[4];
    const float* bq   = (const float*)d_in[5];
    const float* Wk   = (const float*)d_in[6];
    const float* bk   = (const float*)d_in[7];
    const float* Wv   = (const float*)d_in[8];
    const float* bv   = (const float*)d_in[9];
    const float* Wo   = (const float*)d_in[10];
    const float* bo   = (const float*)d_in[11];
    float* out = (float*)d_out;

    dim3 ggrid(1024 / 128, M_ / 128);   // (8, 64)
    gemm_tf32<<<ggrid, 256>>>(q, Wq, bq, nullptr, 0);
    gemm_tf32<<<ggrid, 256>>>(k, Wk, bk, nullptr, 1);
    gemm_tf32<<<ggrid, 256>>>(v, Wv, bv, nullptr, 2);
    attn_tf32<<<B_ * H_ * (S_ / 128), 128>>>(mask);
    gemm_tf32<<<ggrid, 256>>>(nullptr, Wo, bo, out, 3);
}